// round 8
// baseline (speedup 1.0000x reference)
#include <cuda_runtime.h>
#include <cuda_bf16.h>
#include <math.h>

#define NB    4
#define CCH   64
#define NTOK  16384
#define NH    8
#define DH    64
#define INNER 512
#define EPSV  1e-12f

#define OUT_ELEMS  (NB * CCH * NTOK)   // 4194304
#define ATTN_ELEMS (NB * NH * DH * DH) // 131072

// Scratch (static device globals; no allocation allowed)
__device__ float g_Gpart[256 * CCH * CCH]; // per-block partial Gram matrices
__device__ float g_G[NB * CCH * CCH];      // reduced Gram per batch
__device__ float g_M[NB * CCH * CCH];      // effective 64x64 matrix per batch (fp32)

// ---------------- mma / ldmatrix helpers ----------------
__device__ __forceinline__ unsigned cvs(const void* p) {
    return (unsigned)__cvta_generic_to_shared(p);
}
__device__ __forceinline__ void ldm_x4(unsigned r[4], unsigned addr) {
    asm volatile("ldmatrix.sync.aligned.m8n8.x4.shared.b16 {%0,%1,%2,%3}, [%4];"
                 : "=r"(r[0]), "=r"(r[1]), "=r"(r[2]), "=r"(r[3]) : "r"(addr));
}
__device__ __forceinline__ void ldm_x4t(unsigned r[4], unsigned addr) {
    asm volatile("ldmatrix.sync.aligned.m8n8.x4.trans.shared.b16 {%0,%1,%2,%3}, [%4];"
                 : "=r"(r[0]), "=r"(r[1]), "=r"(r[2]), "=r"(r[3]) : "r"(addr));
}
__device__ __forceinline__ void mma_bf16(float c[4], const unsigned a[4], const unsigned b0,
                                         const unsigned b1) {
    asm volatile(
        "mma.sync.aligned.m16n8k16.row.col.f32.bf16.bf16.f32 "
        "{%0,%1,%2,%3}, {%4,%5,%6,%7}, {%8,%9}, {%0,%1,%2,%3};"
        : "+f"(c[0]), "+f"(c[1]), "+f"(c[2]), "+f"(c[3])
        : "r"(a[0]), "r"(a[1]), "r"(a[2]), "r"(a[3]), "r"(b0), "r"(b1));
}
// split two floats into packed bf16x2 hi and lo
__device__ __forceinline__ void split2(float a, float b, unsigned& hi2, unsigned& lo2) {
    unsigned h, l;
    asm("cvt.rn.bf16x2.f32 %0, %1, %2;" : "=r"(h) : "f"(b), "f"(a));
    const float ha = __uint_as_float(h << 16);
    const float hb = __uint_as_float(h & 0xFFFF0000u);
    const float la = a - ha, lb = b - hb;
    asm("cvt.rn.bf16x2.f32 %0, %1, %2;" : "=r"(l) : "f"(lb), "f"(la));
    hi2 = h; lo2 = l;
}

// ---------------------------------------------------------------------------
// K1: partial Gram via bf16-split tensor MMA.
// grid = 256 (4 batches x 64 chunks of 256 tokens), 256 threads (8 warps).
// B-frags fetched pairwise with ldmatrix.x4 (two n-tiles per op).
// ---------------------------------------------------------------------------
#define XS_STRIDE 264
#define K1_SBYTES (2 * 64 * XS_STRIDE * 2) // 67584

__global__ __launch_bounds__(256) void gram_kernel(const float* __restrict__ x) {
    extern __shared__ unsigned short sm1[];
    unsigned short* xhi = sm1;
    unsigned short* xlo = sm1 + 64 * XS_STRIDE;

    const int b     = blockIdx.x >> 6;
    const int chunk = blockIdx.x & 63;
    const int n0    = chunk * 256;
    const int tid   = threadIdx.x;
    const int lane  = tid & 31;
    const int wid   = tid >> 5;

    const float* xb = x + (size_t)b * CCH * NTOK;

#pragma unroll
    for (int r = 0; r < 16; ++r) {
        const int q  = r * 256 + tid;
        const int c  = q >> 6;
        const int t4 = q & 63;
        const float4 v = *reinterpret_cast<const float4*>(&xb[c * NTOK + n0 + 4 * t4]);
        unsigned h0, l0, h1, l1;
        split2(v.x, v.y, h0, l0);
        split2(v.z, v.w, h1, l1);
        *reinterpret_cast<uint2*>(&xhi[c * XS_STRIDE + 4 * t4]) = make_uint2(h0, h1);
        *reinterpret_cast<uint2*>(&xlo[c * XS_STRIDE + 4 * t4]) = make_uint2(l0, l1);
    }
    __syncthreads();

    const int mt  = wid & 3;       // c1 tile (16 rows)
    const int ntb = 4 * (wid >> 2); // c2 tile base (4 tiles of 8)

    float acc[4][4];
#pragma unroll
    for (int j = 0; j < 4; ++j)
#pragma unroll
        for (int k = 0; k < 4; ++k) acc[j][k] = 0.f;

    // A-frag lane address (16x16 tile, row-major)
    const int aq   = lane >> 3;
    const int arow = 16 * mt + (aq & 1) * 8 + (lane & 7);
    const int acol_off = (aq >> 1) * 8;
    // B-frag x4 lane address: two 8-row n-tiles from [n][k] layout
    //   row = N0 + ((lane>>4)<<3) + (lane&7), col = K0 + (((lane>>3)&1)<<3)
    const int brow_off = ((lane >> 4) << 3) + (lane & 7);
    const int bcol_off = ((lane >> 3) & 1) << 3;

#pragma unroll 4
    for (int kt = 0; kt < 16; ++kt) {
        const int K0 = 16 * kt;
        unsigned Ahi[4], Alo[4];
        ldm_x4(Ahi, cvs(&xhi[arow * XS_STRIDE + K0 + acol_off]));
        ldm_x4(Alo, cvs(&xlo[arow * XS_STRIDE + K0 + acol_off]));
#pragma unroll
        for (int p = 0; p < 2; ++p) {
            const int N0 = 8 * (ntb + 2 * p);
            unsigned Bhi[4], Blo[4];
            ldm_x4(Bhi, cvs(&xhi[(N0 + brow_off) * XS_STRIDE + K0 + bcol_off]));
            ldm_x4(Blo, cvs(&xlo[(N0 + brow_off) * XS_STRIDE + K0 + bcol_off]));
            mma_bf16(acc[2 * p],     Ahi, Bhi[0], Bhi[1]);
            mma_bf16(acc[2 * p],     Ahi, Blo[0], Blo[1]);
            mma_bf16(acc[2 * p],     Alo, Bhi[0], Bhi[1]);
            mma_bf16(acc[2 * p + 1], Ahi, Bhi[2], Bhi[3]);
            mma_bf16(acc[2 * p + 1], Ahi, Blo[2], Blo[3]);
            mma_bf16(acc[2 * p + 1], Alo, Bhi[2], Bhi[3]);
        }
    }

    float* gp = g_Gpart + (size_t)blockIdx.x * 4096;
    const int g = lane >> 2, l = lane & 3;
#pragma unroll
    for (int j = 0; j < 4; ++j) {
        const int col0 = 8 * (ntb + j) + 2 * l;
        const int row0 = 16 * mt + g;
        *reinterpret_cast<float2*>(&gp[row0 * 64 + col0])       = make_float2(acc[j][0], acc[j][1]);
        *reinterpret_cast<float2*>(&gp[(row0 + 8) * 64 + col0]) = make_float2(acc[j][2], acc[j][3]);
    }
}

// ---------------------------------------------------------------------------
// K1b: reduce 64 partials per batch into g_G; also zero g_M.
// ---------------------------------------------------------------------------
__global__ __launch_bounds__(256) void reduce_gram_kernel() {
    const int i = blockIdx.x * 256 + threadIdx.x;
    const int b = i >> 12;
    const int idx = i & 4095;
    float s = 0.f;
    const float* gp = g_Gpart + (size_t)(b * 64) * 4096 + idx;
#pragma unroll 8
    for (int p = 0; p < 64; ++p) s += gp[(size_t)p * 4096];
    g_G[i] = s;
    g_M[i] = 0.f;
}

// ---------------------------------------------------------------------------
// K2: per (batch, head, d-half) attention math. (unchanged from R7)
// ---------------------------------------------------------------------------
#define S2 68
#define K2_SFLOATS (4 * 64 * S2 + 32 * S2 + 256 + 64 + 32)
#define K2_SBYTES  (K2_SFLOATS * 4)

__global__ __launch_bounds__(256) void attn_small_kernel(
    const float* __restrict__ Wq, const float* __restrict__ Wk,
    const float* __restrict__ Wv, const float* __restrict__ Wp,
    const float* __restrict__ rescale, float* __restrict__ attn_out) {
    extern __shared__ float smem[];
    float* sG  = smem;
    float* sA  = smem + 64 * S2;
    float* sB  = smem + 2 * 64 * S2;
    float* sT  = smem + 3 * 64 * S2;
    float* sS  = smem + 4 * 64 * S2;
    float* red = sS + 32 * S2;
    float* snq = red + 256;
    float* snk = snq + 64;

    const int bx   = blockIdx.x;
    const int b    = bx >> 4;
    const int h    = (bx >> 1) & 7;
    const int half = bx & 1;
    const int d0   = half * 32;
    const int tid  = threadIdx.x;
    const int ty   = tid >> 4;
    const int tx   = tid & 15;

#pragma unroll
    for (int r = 0; r < 4; ++r) {
        const int q    = r * 256 + tid;
        const int row  = q >> 4;
        const int col4 = (q & 15) * 4;
        *reinterpret_cast<float4*>(&sG[row * S2 + col4]) =
            *reinterpret_cast<const float4*>(&g_G[b * 4096 + row * 64 + col4]);
        *reinterpret_cast<float4*>(&sA[row * S2 + col4]) =
            *reinterpret_cast<const float4*>(&Wq[row * INNER + h * 64 + col4]);
        *reinterpret_cast<float4*>(&sB[row * S2 + col4]) =
            *reinterpret_cast<const float4*>(&Wk[row * INNER + h * 64 + col4]);
    }
    __syncthreads();

    {
        float acc[4][4];
#pragma unroll
        for (int i = 0; i < 4; ++i)
#pragma unroll
            for (int j = 0; j < 4; ++j) acc[i][j] = 0.f;
#pragma unroll 4
        for (int cp = 0; cp < 64; ++cp) {
            const float4 a4 = *reinterpret_cast<const float4*>(&sG[cp * S2 + 4 * ty]);
            const float4 b4 = *reinterpret_cast<const float4*>(&sA[cp * S2 + 4 * tx]);
            const float a[4] = {a4.x, a4.y, a4.z, a4.w};
            const float bb[4] = {b4.x, b4.y, b4.z, b4.w};
#pragma unroll
            for (int i = 0; i < 4; ++i)
#pragma unroll
                for (int j = 0; j < 4; ++j) acc[i][j] = fmaf(a[i], bb[j], acc[i][j]);
        }
#pragma unroll
        for (int i = 0; i < 4; ++i)
            *reinterpret_cast<float4*>(&sT[(4 * ty + i) * S2 + 4 * tx]) =
                make_float4(acc[i][0], acc[i][1], acc[i][2], acc[i][3]);
    }
    __syncthreads();

    {
        const int e = tid & 63, p = tid >> 6;
        float s = 0.f;
        for (int c = p * 16; c < p * 16 + 16; ++c) s += sA[c * S2 + e] * sT[c * S2 + e];
        red[p * 64 + e] = s;
    }
    __syncthreads();
    if (tid < 64) snq[tid] = sqrtf(red[tid] + red[64 + tid] + red[128 + tid] + red[192 + tid]);
    __syncthreads();

    {
        float acc[2][4] = {{0.f,0.f,0.f,0.f},{0.f,0.f,0.f,0.f}};
#pragma unroll 4
        for (int cp = 0; cp < 64; ++cp) {
            const float2 a2 = *reinterpret_cast<const float2*>(&sB[cp * S2 + d0 + 2 * ty]);
            const float4 b4 = *reinterpret_cast<const float4*>(&sG[cp * S2 + 4 * tx]);
            const float a[2] = {a2.x, a2.y};
            const float bb[4] = {b4.x, b4.y, b4.z, b4.w};
#pragma unroll
            for (int i = 0; i < 2; ++i)
#pragma unroll
                for (int j = 0; j < 4; ++j) acc[i][j] = fmaf(a[i], bb[j], acc[i][j]);
        }
#pragma unroll
        for (int i = 0; i < 2; ++i)
            *reinterpret_cast<float4*>(&sS[(2 * ty + i) * S2 + 4 * tx]) =
                make_float4(acc[i][0], acc[i][1], acc[i][2], acc[i][3]);
    }
    __syncthreads();

    {
        const int d = tid & 31, p = tid >> 5;
        float s = 0.f;
        for (int c = p * 8; c < p * 8 + 8; ++c) s += sB[c * S2 + d0 + d] * sS[d * S2 + c];
        red[p * 32 + d] = s;
    }
    __syncthreads();
    if (tid < 32) {
        float s = 0.f;
#pragma unroll
        for (int p = 0; p < 8; ++p) s += red[p * 32 + tid];
        snk[tid] = sqrtf(s);
    }
    __syncthreads();

    {
        float acc[2][4] = {{0.f,0.f,0.f,0.f},{0.f,0.f,0.f,0.f}};
#pragma unroll 4
        for (int cp = 0; cp < 64; ++cp) {
            const float2 a2 = *reinterpret_cast<const float2*>(&sB[cp * S2 + d0 + 2 * ty]);
            const float4 b4 = *reinterpret_cast<const float4*>(&sT[cp * S2 + 4 * tx]);
            const float a[2] = {a2.x, a2.y};
            const float bb[4] = {b4.x, b4.y, b4.z, b4.w};
#pragma unroll
            for (int i = 0; i < 2; ++i)
#pragma unroll
                for (int j = 0; j < 4; ++j) acc[i][j] = fmaf(a[i], bb[j], acc[i][j]);
        }
        const float rs = rescale[h];
        __syncthreads();
#pragma unroll
        for (int i = 0; i < 2; ++i)
#pragma unroll
            for (int j = 0; j < 4; ++j) {
                const int d = 2 * ty + i, e = 4 * tx + j;
                sS[d * S2 + e] = acc[i][j] * rs /
                                 (fmaxf(snk[d], EPSV) * fmaxf(snq[e], EPSV));
            }
    }
    __syncthreads();

    {
        const int w = tid >> 5, lane = tid & 31;
        for (int r = 0; r < 4; ++r) {
            const int d = w * 4 + r;
            float v0 = sS[d * S2 + lane];
            float v1 = sS[d * S2 + 32 + lane];
            float m = fmaxf(v0, v1);
#pragma unroll
            for (int o = 16; o > 0; o >>= 1) m = fmaxf(m, __shfl_xor_sync(0xffffffffu, m, o));
            float e0 = __expf(v0 - m), e1 = __expf(v1 - m);
            float s = e0 + e1;
#pragma unroll
            for (int o = 16; o > 0; o >>= 1) s += __shfl_xor_sync(0xffffffffu, s, o);
            const float inv = 1.f / s;
            e0 *= inv; e1 *= inv;
            sS[d * S2 + lane]      = e0;
            sS[d * S2 + 32 + lane] = e1;
            float* ao = attn_out + (((size_t)(b * NH + h) * DH) + d0 + d) * DH;
            ao[lane]      = e0;
            ao[32 + lane] = e1;
        }
    }
    __syncthreads();

    for (int r = 0; r < 16; ++r) {
        const int idx = r * 256 + tid;
        const int c = idx >> 6, e = idx & 63;
        sA[e * S2 + c] = Wv[c * INNER + h * 64 + e];
    }
#pragma unroll
    for (int r = 0; r < 2; ++r) {
        const int q    = r * 256 + tid;
        const int d    = q >> 4;
        const int col4 = (q & 15) * 4;
        *reinterpret_cast<float4*>(&sB[d * S2 + col4]) =
            *reinterpret_cast<const float4*>(&Wp[(h * 64 + d0 + d) * CCH + col4]);
    }
    __syncthreads();

    {
        float acc[4][4];
#pragma unroll
        for (int i = 0; i < 4; ++i)
#pragma unroll
            for (int j = 0; j < 4; ++j) acc[i][j] = 0.f;
#pragma unroll 4
        for (int dk = 0; dk < 32; ++dk) {
            const float4 a4 = *reinterpret_cast<const float4*>(&sS[dk * S2 + 4 * ty]);
            const float4 b4 = *reinterpret_cast<const float4*>(&sB[dk * S2 + 4 * tx]);
            const float a[4] = {a4.x, a4.y, a4.z, a4.w};
            const float bb[4] = {b4.x, b4.y, b4.z, b4.w};
#pragma unroll
            for (int i = 0; i < 4; ++i)
#pragma unroll
                for (int j = 0; j < 4; ++j) acc[i][j] = fmaf(a[i], bb[j], acc[i][j]);
        }
#pragma unroll
        for (int i = 0; i < 4; ++i)
            *reinterpret_cast<float4*>(&sT[(4 * ty + i) * S2 + 4 * tx]) =
                make_float4(acc[i][0], acc[i][1], acc[i][2], acc[i][3]);
    }
    __syncthreads();

    {
        float acc[4][4];
#pragma unroll
        for (int i = 0; i < 4; ++i)
#pragma unroll
            for (int j = 0; j < 4; ++j) acc[i][j] = 0.f;
#pragma unroll 4
        for (int e = 0; e < 64; ++e) {
            const float4 a4 = *reinterpret_cast<const float4*>(&sA[e * S2 + 4 * ty]);
            const float4 b4 = *reinterpret_cast<const float4*>(&sT[e * S2 + 4 * tx]);
            const float a[4] = {a4.x, a4.y, a4.z, a4.w};
            const float bb[4] = {b4.x, b4.y, b4.z, b4.w};
#pragma unroll
            for (int i = 0; i < 4; ++i)
#pragma unroll
                for (int j = 0; j < 4; ++j) acc[i][j] = fmaf(a[i], bb[j], acc[i][j]);
        }
#pragma unroll
        for (int i = 0; i < 4; ++i)
#pragma unroll
            for (int j = 0; j < 4; ++j)
                atomicAdd(&g_M[b * 4096 + (4 * ty + i) * 64 + (4 * tx + j)], acc[i][j]);
    }
}

// ---------------------------------------------------------------------------
// K3: out = M^T @ x via bf16-split tensor MMA.
// grid = 512 (4 batches x 128 segments of 128 tokens), 256 threads.
// B-frags via ldmatrix.x4.trans (two token-tiles per op); smem 52KB -> 4 CTA/SM.
// ---------------------------------------------------------------------------
#define X3_STRIDE 136
#define MT_STRIDE 72
#define K3_SBYTES (2 * 64 * X3_STRIDE * 2 + 2 * 64 * MT_STRIDE * 2) // 34816+18432=53248

__global__ __launch_bounds__(256) void out_kernel(const float* __restrict__ x,
                                                  const float* __restrict__ bp,
                                                  float* __restrict__ out) {
    extern __shared__ unsigned short sm3[];
    unsigned short* xhi = sm3;
    unsigned short* xlo = sm3 + 64 * X3_STRIDE;
    unsigned short* mhi = sm3 + 2 * 64 * X3_STRIDE;
    unsigned short* mlo = mhi + 64 * MT_STRIDE;

    const int b    = blockIdx.x >> 7;
    const int seg  = blockIdx.x & 127;
    const int n0   = seg * 128;
    const int tid  = threadIdx.x;
    const int lane = tid & 31;
    const int wid  = tid >> 5;

    const float* xb = x + (size_t)b * CCH * NTOK;
    float* ob = out + (size_t)b * CCH * NTOK;

    // fill x tile (convert to hi/lo): 2048 f4 / 256 thr = 8 each
#pragma unroll
    for (int r = 0; r < 8; ++r) {
        const int q  = r * 256 + tid;
        const int c  = q >> 5;
        const int t4 = q & 31;
        const float4 v = *reinterpret_cast<const float4*>(&xb[c * NTOK + n0 + 4 * t4]);
        unsigned h0, l0, h1, l1;
        split2(v.x, v.y, h0, l0);
        split2(v.z, v.w, h1, l1);
        *reinterpret_cast<uint2*>(&xhi[c * X3_STRIDE + 4 * t4]) = make_uint2(h0, h1);
        *reinterpret_cast<uint2*>(&xlo[c * X3_STRIDE + 4 * t4]) = make_uint2(l0, l1);
    }
    // fill Mt tiles: read fp32 g_M [cp][c], split + transpose -> [c][cp]
#pragma unroll
    for (int r = 0; r < 16; ++r) {
        const int q  = r * 256 + tid;   // 0..4095
        const int cp = q >> 6, c = q & 63;
        const float v = g_M[b * 4096 + q];
        const __nv_bfloat16 hh = __float2bfloat16(v);
        const __nv_bfloat16 ll = __float2bfloat16(v - __bfloat162float(hh));
        mhi[c * MT_STRIDE + cp] = __bfloat16_as_ushort(hh);
        mlo[c * MT_STRIDE + cp] = __bfloat16_as_ushort(ll);
    }
    __syncthreads();

    const int mt = wid & 3;         // c tile (16 rows)
    const int tg = wid >> 2;        // token group (64 tokens each)

    float acc[8][4];
#pragma unroll
    for (int j = 0; j < 8; ++j)
#pragma unroll
        for (int k = 0; k < 4; ++k) acc[j][k] = 0.f;

    const int aq   = lane >> 3;
    const int arow = 16 * mt + (aq & 1) * 8 + (lane & 7);
    const int acol_off = (aq >> 1) * 8;
    // B x4t lane address: row = K0 + (lane&15), col = T0 + ((lane>>4)<<3)
    const int bkrow = lane & 15;
    const int btcol = (lane >> 4) << 3;

#pragma unroll
    for (int kt = 0; kt < 4; ++kt) {
        const int K0 = 16 * kt;
        unsigned Ahi[4], Alo[4];
        ldm_x4(Ahi, cvs(&mhi[arow * MT_STRIDE + K0 + acol_off]));
        ldm_x4(Alo, cvs(&mlo[arow * MT_STRIDE + K0 + acol_off]));
        const int brow = K0 + bkrow;
#pragma unroll
        for (int p = 0; p < 4; ++p) {
            const int T0 = 64 * tg + 16 * p;
            unsigned Bhi[4], Blo[4];
            ldm_x4t(Bhi, cvs(&xhi[brow * X3_STRIDE + T0 + btcol]));
            ldm_x4t(Blo, cvs(&xlo[brow * X3_STRIDE + T0 + btcol]));
            mma_bf16(acc[2 * p],     Ahi, Bhi[0], Bhi[1]);
            mma_bf16(acc[2 * p],     Ahi, Blo[0], Blo[1]);
            mma_bf16(acc[2 * p],     Alo, Bhi[0], Bhi[1]);
            mma_bf16(acc[2 * p + 1], Ahi, Bhi[2], Bhi[3]);
            mma_bf16(acc[2 * p + 1], Ahi, Blo[2], Blo[3]);
            mma_bf16(acc[2 * p + 1], Alo, Bhi[2], Bhi[3]);
        }
    }

    const int g = lane >> 2, l = lane & 3;
    const int r0 = 16 * mt + g;
    const float bp0 = bp[r0], bp1 = bp[r0 + 8];
#pragma unroll
    for (int j = 0; j < 8; ++j) {
        const int tok = n0 + 64 * tg + 8 * j + 2 * l;
        *reinterpret_cast<float2*>(&ob[r0 * NTOK + tok]) =
            make_float2(acc[j][0] + bp0, acc[j][1] + bp0);
        *reinterpret_cast<float2*>(&ob[(r0 + 8) * NTOK + tok]) =
            make_float2(acc[j][2] + bp1, acc[j][3] + bp1);
    }
}

// ---------------------------------------------------------------------------
extern "C" void kernel_launch(void* const* d_in, const int* in_sizes, int n_in,
                              void* d_out, int out_size) {
    const float* x       = (const float*)d_in[0];
    const float* Wq      = (const float*)d_in[1];
    const float* Wk      = (const float*)d_in[2];
    const float* Wv      = (const float*)d_in[3];
    const float* Wp      = (const float*)d_in[4];
    const float* bp      = (const float*)d_in[5];
    const float* rescale = (const float*)d_in[6];
    float* out      = (float*)d_out;
    float* attn_out = out + OUT_ELEMS;

    cudaFuncSetAttribute(gram_kernel,
                         cudaFuncAttributeMaxDynamicSharedMemorySize, K1_SBYTES);
    cudaFuncSetAttribute(attn_small_kernel,
                         cudaFuncAttributeMaxDynamicSharedMemorySize, K2_SBYTES);
    cudaFuncSetAttribute(out_kernel,
                         cudaFuncAttributeMaxDynamicSharedMemorySize, K3_SBYTES);

    gram_kernel<<<256, 256, K1_SBYTES>>>(x);
    reduce_gram_kernel<<<64, 256>>>();
    attn_small_kernel<<<64, 256, K2_SBYTES>>>(Wq, Wk, Wv, Wp, rescale, attn_out);
    out_kernel<<<512, 256, K3_SBYTES>>>(x, bp, out);
}

// round 9
// speedup vs baseline: 1.3954x; 1.3954x over previous
#include <cuda_runtime.h>
#include <cuda_bf16.h>
#include <math.h>

#define NB    4
#define CCH   64
#define NTOK  16384
#define NH    8
#define DH    64
#define INNER 512
#define EPSV  1e-12f

#define OUT_ELEMS  (NB * CCH * NTOK)   // 4194304
#define ATTN_ELEMS (NB * NH * DH * DH) // 131072

// Scratch (static device globals; no allocation allowed)
__device__ float g_Gpart[256 * CCH * CCH]; // per-block partial Gram matrices
__device__ float g_G[NB * CCH * CCH];      // reduced Gram per batch
__device__ float g_M[NB * CCH * CCH];      // effective 64x64 matrix per batch (fp32)

// ---------------- mma / ldmatrix helpers ----------------
__device__ __forceinline__ unsigned cvs(const void* p) {
    return (unsigned)__cvta_generic_to_shared(p);
}
__device__ __forceinline__ void ldm_x4(unsigned r[4], unsigned addr) {
    asm volatile("ldmatrix.sync.aligned.m8n8.x4.shared.b16 {%0,%1,%2,%3}, [%4];"
                 : "=r"(r[0]), "=r"(r[1]), "=r"(r[2]), "=r"(r[3]) : "r"(addr));
}
__device__ __forceinline__ void ldm_x4t(unsigned r[4], unsigned addr) {
    asm volatile("ldmatrix.sync.aligned.m8n8.x4.trans.shared.b16 {%0,%1,%2,%3}, [%4];"
                 : "=r"(r[0]), "=r"(r[1]), "=r"(r[2]), "=r"(r[3]) : "r"(addr));
}
__device__ __forceinline__ void mma_bf16(float c[4], const unsigned a[4], const unsigned b0,
                                         const unsigned b1) {
    asm volatile(
        "mma.sync.aligned.m16n8k16.row.col.f32.bf16.bf16.f32 "
        "{%0,%1,%2,%3}, {%4,%5,%6,%7}, {%8,%9}, {%0,%1,%2,%3};"
        : "+f"(c[0]), "+f"(c[1]), "+f"(c[2]), "+f"(c[3])
        : "r"(a[0]), "r"(a[1]), "r"(a[2]), "r"(a[3]), "r"(b0), "r"(b1));
}
// split two floats into packed bf16x2 hi and lo
__device__ __forceinline__ void split2(float a, float b, unsigned& hi2, unsigned& lo2) {
    unsigned h, l;
    asm("cvt.rn.bf16x2.f32 %0, %1, %2;" : "=r"(h) : "f"(b), "f"(a));
    const float ha = __uint_as_float(h << 16);
    const float hb = __uint_as_float(h & 0xFFFF0000u);
    const float la = a - ha, lb = b - hb;
    asm("cvt.rn.bf16x2.f32 %0, %1, %2;" : "=r"(l) : "f"(lb), "f"(la));
    hi2 = h; lo2 = l;
}

// ---------------------------------------------------------------------------
// K1: partial Gram via bf16-split tensor MMA.
// grid = 256 (4 batches x 64 chunks of 256 tokens), 256 threads (8 warps).
// B-frags fetched pairwise with ldmatrix.x4; __launch_bounds__(256,2)
// pins regs to 128 (R8 regression was ptxas dropping to 64 regs -> spills).
// ---------------------------------------------------------------------------
#define XS_STRIDE 264
#define K1_SBYTES (2 * 64 * XS_STRIDE * 2) // 67584

__global__ __launch_bounds__(256, 2) void gram_kernel(const float* __restrict__ x) {
    extern __shared__ unsigned short sm1[];
    unsigned short* xhi = sm1;
    unsigned short* xlo = sm1 + 64 * XS_STRIDE;

    const int b     = blockIdx.x >> 6;
    const int chunk = blockIdx.x & 63;
    const int n0    = chunk * 256;
    const int tid   = threadIdx.x;
    const int lane  = tid & 31;
    const int wid   = tid >> 5;

    const float* xb = x + (size_t)b * CCH * NTOK;

#pragma unroll
    for (int r = 0; r < 16; ++r) {
        const int q  = r * 256 + tid;
        const int c  = q >> 6;
        const int t4 = q & 63;
        const float4 v = *reinterpret_cast<const float4*>(&xb[c * NTOK + n0 + 4 * t4]);
        unsigned h0, l0, h1, l1;
        split2(v.x, v.y, h0, l0);
        split2(v.z, v.w, h1, l1);
        *reinterpret_cast<uint2*>(&xhi[c * XS_STRIDE + 4 * t4]) = make_uint2(h0, h1);
        *reinterpret_cast<uint2*>(&xlo[c * XS_STRIDE + 4 * t4]) = make_uint2(l0, l1);
    }
    __syncthreads();

    const int mt  = wid & 3;        // c1 tile (16 rows)
    const int ntb = 4 * (wid >> 2); // c2 tile base (4 tiles of 8)

    float acc[4][4];
#pragma unroll
    for (int j = 0; j < 4; ++j)
#pragma unroll
        for (int k = 0; k < 4; ++k) acc[j][k] = 0.f;

    // A-frag lane address (16x16 tile, row-major)
    const int aq   = lane >> 3;
    const int arow = 16 * mt + (aq & 1) * 8 + (lane & 7);
    const int acol_off = (aq >> 1) * 8;
    // B-frag x4 lane address: two 8-row n-tiles from [n][k] layout
    const int brow_off = ((lane >> 4) << 3) + (lane & 7);
    const int bcol_off = ((lane >> 3) & 1) << 3;

#pragma unroll 4
    for (int kt = 0; kt < 16; ++kt) {
        const int K0 = 16 * kt;
        unsigned Ahi[4], Alo[4];
        ldm_x4(Ahi, cvs(&xhi[arow * XS_STRIDE + K0 + acol_off]));
        ldm_x4(Alo, cvs(&xlo[arow * XS_STRIDE + K0 + acol_off]));
#pragma unroll
        for (int p = 0; p < 2; ++p) {
            const int N0 = 8 * (ntb + 2 * p);
            unsigned Bhi[4], Blo[4];
            ldm_x4(Bhi, cvs(&xhi[(N0 + brow_off) * XS_STRIDE + K0 + bcol_off]));
            ldm_x4(Blo, cvs(&xlo[(N0 + brow_off) * XS_STRIDE + K0 + bcol_off]));
            mma_bf16(acc[2 * p],     Ahi, Bhi[0], Bhi[1]);
            mma_bf16(acc[2 * p],     Ahi, Blo[0], Blo[1]);
            mma_bf16(acc[2 * p],     Alo, Bhi[0], Bhi[1]);
            mma_bf16(acc[2 * p + 1], Ahi, Bhi[2], Bhi[3]);
            mma_bf16(acc[2 * p + 1], Ahi, Blo[2], Blo[3]);
            mma_bf16(acc[2 * p + 1], Alo, Bhi[2], Bhi[3]);
        }
    }

    float* gp = g_Gpart + (size_t)blockIdx.x * 4096;
    const int g = lane >> 2, l = lane & 3;
#pragma unroll
    for (int j = 0; j < 4; ++j) {
        const int col0 = 8 * (ntb + j) + 2 * l;
        const int row0 = 16 * mt + g;
        *reinterpret_cast<float2*>(&gp[row0 * 64 + col0])       = make_float2(acc[j][0], acc[j][1]);
        *reinterpret_cast<float2*>(&gp[(row0 + 8) * 64 + col0]) = make_float2(acc[j][2], acc[j][3]);
    }
}

// ---------------------------------------------------------------------------
// K1b: reduce 64 partials per batch into g_G (float4); also zero g_M.
// grid = 16 x 256 threads -> 4096 float4 lanes.
// ---------------------------------------------------------------------------
__global__ __launch_bounds__(256) void reduce_gram_kernel() {
    const int i = blockIdx.x * 256 + threadIdx.x; // 0..4095 (float4 index)
    const int b = i >> 10;                         // 1024 f4 per batch
    const int idx = i & 1023;
    float4 s = make_float4(0.f, 0.f, 0.f, 0.f);
    const float4* gp = reinterpret_cast<const float4*>(g_Gpart) + (size_t)(b * 64) * 1024 + idx;
#pragma unroll 8
    for (int p = 0; p < 64; ++p) {
        const float4 v = gp[(size_t)p * 1024];
        s.x += v.x; s.y += v.y; s.z += v.z; s.w += v.w;
    }
    reinterpret_cast<float4*>(g_G)[i] = s;
    reinterpret_cast<float4*>(g_M)[i] = make_float4(0.f, 0.f, 0.f, 0.f);
}

// ---------------------------------------------------------------------------
// K2: per (batch, head, d-half) attention math. (unchanged from R7)
// ---------------------------------------------------------------------------
#define S2 68
#define K2_SFLOATS (4 * 64 * S2 + 32 * S2 + 256 + 64 + 32)
#define K2_SBYTES  (K2_SFLOATS * 4)

__global__ __launch_bounds__(256) void attn_small_kernel(
    const float* __restrict__ Wq, const float* __restrict__ Wk,
    const float* __restrict__ Wv, const float* __restrict__ Wp,
    const float* __restrict__ rescale, float* __restrict__ attn_out) {
    extern __shared__ float smem[];
    float* sG  = smem;
    float* sA  = smem + 64 * S2;
    float* sB  = smem + 2 * 64 * S2;
    float* sT  = smem + 3 * 64 * S2;
    float* sS  = smem + 4 * 64 * S2;
    float* red = sS + 32 * S2;
    float* snq = red + 256;
    float* snk = snq + 64;

    const int bx   = blockIdx.x;
    const int b    = bx >> 4;
    const int h    = (bx >> 1) & 7;
    const int half = bx & 1;
    const int d0   = half * 32;
    const int tid  = threadIdx.x;
    const int ty   = tid >> 4;
    const int tx   = tid & 15;

#pragma unroll
    for (int r = 0; r < 4; ++r) {
        const int q    = r * 256 + tid;
        const int row  = q >> 4;
        const int col4 = (q & 15) * 4;
        *reinterpret_cast<float4*>(&sG[row * S2 + col4]) =
            *reinterpret_cast<const float4*>(&g_G[b * 4096 + row * 64 + col4]);
        *reinterpret_cast<float4*>(&sA[row * S2 + col4]) =
            *reinterpret_cast<const float4*>(&Wq[row * INNER + h * 64 + col4]);
        *reinterpret_cast<float4*>(&sB[row * S2 + col4]) =
            *reinterpret_cast<const float4*>(&Wk[row * INNER + h * 64 + col4]);
    }
    __syncthreads();

    {
        float acc[4][4];
#pragma unroll
        for (int i = 0; i < 4; ++i)
#pragma unroll
            for (int j = 0; j < 4; ++j) acc[i][j] = 0.f;
#pragma unroll 4
        for (int cp = 0; cp < 64; ++cp) {
            const float4 a4 = *reinterpret_cast<const float4*>(&sG[cp * S2 + 4 * ty]);
            const float4 b4 = *reinterpret_cast<const float4*>(&sA[cp * S2 + 4 * tx]);
            const float a[4] = {a4.x, a4.y, a4.z, a4.w};
            const float bb[4] = {b4.x, b4.y, b4.z, b4.w};
#pragma unroll
            for (int i = 0; i < 4; ++i)
#pragma unroll
                for (int j = 0; j < 4; ++j) acc[i][j] = fmaf(a[i], bb[j], acc[i][j]);
        }
#pragma unroll
        for (int i = 0; i < 4; ++i)
            *reinterpret_cast<float4*>(&sT[(4 * ty + i) * S2 + 4 * tx]) =
                make_float4(acc[i][0], acc[i][1], acc[i][2], acc[i][3]);
    }
    __syncthreads();

    {
        const int e = tid & 63, p = tid >> 6;
        float s = 0.f;
        for (int c = p * 16; c < p * 16 + 16; ++c) s += sA[c * S2 + e] * sT[c * S2 + e];
        red[p * 64 + e] = s;
    }
    __syncthreads();
    if (tid < 64) snq[tid] = sqrtf(red[tid] + red[64 + tid] + red[128 + tid] + red[192 + tid]);
    __syncthreads();

    {
        float acc[2][4] = {{0.f,0.f,0.f,0.f},{0.f,0.f,0.f,0.f}};
#pragma unroll 4
        for (int cp = 0; cp < 64; ++cp) {
            const float2 a2 = *reinterpret_cast<const float2*>(&sB[cp * S2 + d0 + 2 * ty]);
            const float4 b4 = *reinterpret_cast<const float4*>(&sG[cp * S2 + 4 * tx]);
            const float a[2] = {a2.x, a2.y};
            const float bb[4] = {b4.x, b4.y, b4.z, b4.w};
#pragma unroll
            for (int i = 0; i < 2; ++i)
#pragma unroll
                for (int j = 0; j < 4; ++j) acc[i][j] = fmaf(a[i], bb[j], acc[i][j]);
        }
#pragma unroll
        for (int i = 0; i < 2; ++i)
            *reinterpret_cast<float4*>(&sS[(2 * ty + i) * S2 + 4 * tx]) =
                make_float4(acc[i][0], acc[i][1], acc[i][2], acc[i][3]);
    }
    __syncthreads();

    {
        const int d = tid & 31, p = tid >> 5;
        float s = 0.f;
        for (int c = p * 8; c < p * 8 + 8; ++c) s += sB[c * S2 + d0 + d] * sS[d * S2 + c];
        red[p * 32 + d] = s;
    }
    __syncthreads();
    if (tid < 32) {
        float s = 0.f;
#pragma unroll
        for (int p = 0; p < 8; ++p) s += red[p * 32 + tid];
        snk[tid] = sqrtf(s);
    }
    __syncthreads();

    {
        float acc[2][4] = {{0.f,0.f,0.f,0.f},{0.f,0.f,0.f,0.f}};
#pragma unroll 4
        for (int cp = 0; cp < 64; ++cp) {
            const float2 a2 = *reinterpret_cast<const float2*>(&sB[cp * S2 + d0 + 2 * ty]);
            const float4 b4 = *reinterpret_cast<const float4*>(&sT[cp * S2 + 4 * tx]);
            const float a[2] = {a2.x, a2.y};
            const float bb[4] = {b4.x, b4.y, b4.z, b4.w};
#pragma unroll
            for (int i = 0; i < 2; ++i)
#pragma unroll
                for (int j = 0; j < 4; ++j) acc[i][j] = fmaf(a[i], bb[j], acc[i][j]);
        }
        const float rs = rescale[h];
        __syncthreads();
#pragma unroll
        for (int i = 0; i < 2; ++i)
#pragma unroll
            for (int j = 0; j < 4; ++j) {
                const int d = 2 * ty + i, e = 4 * tx + j;
                sS[d * S2 + e] = acc[i][j] * rs /
                                 (fmaxf(snk[d], EPSV) * fmaxf(snq[e], EPSV));
            }
    }
    __syncthreads();

    {
        const int w = tid >> 5, lane = tid & 31;
        for (int r = 0; r < 4; ++r) {
            const int d = w * 4 + r;
            float v0 = sS[d * S2 + lane];
            float v1 = sS[d * S2 + 32 + lane];
            float m = fmaxf(v0, v1);
#pragma unroll
            for (int o = 16; o > 0; o >>= 1) m = fmaxf(m, __shfl_xor_sync(0xffffffffu, m, o));
            float e0 = __expf(v0 - m), e1 = __expf(v1 - m);
            float s = e0 + e1;
#pragma unroll
            for (int o = 16; o > 0; o >>= 1) s += __shfl_xor_sync(0xffffffffu, s, o);
            const float inv = 1.f / s;
            e0 *= inv; e1 *= inv;
            sS[d * S2 + lane]      = e0;
            sS[d * S2 + 32 + lane] = e1;
            float* ao = attn_out + (((size_t)(b * NH + h) * DH) + d0 + d) * DH;
            ao[lane]      = e0;
            ao[32 + lane] = e1;
        }
    }
    __syncthreads();

    for (int r = 0; r < 16; ++r) {
        const int idx = r * 256 + tid;
        const int c = idx >> 6, e = idx & 63;
        sA[e * S2 + c] = Wv[c * INNER + h * 64 + e];
    }
#pragma unroll
    for (int r = 0; r < 2; ++r) {
        const int q    = r * 256 + tid;
        const int d    = q >> 4;
        const int col4 = (q & 15) * 4;
        *reinterpret_cast<float4*>(&sB[d * S2 + col4]) =
            *reinterpret_cast<const float4*>(&Wp[(h * 64 + d0 + d) * CCH + col4]);
    }
    __syncthreads();

    {
        float acc[4][4];
#pragma unroll
        for (int i = 0; i < 4; ++i)
#pragma unroll
            for (int j = 0; j < 4; ++j) acc[i][j] = 0.f;
#pragma unroll 4
        for (int dk = 0; dk < 32; ++dk) {
            const float4 a4 = *reinterpret_cast<const float4*>(&sS[dk * S2 + 4 * ty]);
            const float4 b4 = *reinterpret_cast<const float4*>(&sB[dk * S2 + 4 * tx]);
            const float a[4] = {a4.x, a4.y, a4.z, a4.w};
            const float bb[4] = {b4.x, b4.y, b4.z, b4.w};
#pragma unroll
            for (int i = 0; i < 4; ++i)
#pragma unroll
                for (int j = 0; j < 4; ++j) acc[i][j] = fmaf(a[i], bb[j], acc[i][j]);
        }
#pragma unroll
        for (int i = 0; i < 4; ++i)
            *reinterpret_cast<float4*>(&sT[(4 * ty + i) * S2 + 4 * tx]) =
                make_float4(acc[i][0], acc[i][1], acc[i][2], acc[i][3]);
    }
    __syncthreads();

    {
        float acc[4][4];
#pragma unroll
        for (int i = 0; i < 4; ++i)
#pragma unroll
            for (int j = 0; j < 4; ++j) acc[i][j] = 0.f;
#pragma unroll 4
        for (int e = 0; e < 64; ++e) {
            const float4 a4 = *reinterpret_cast<const float4*>(&sA[e * S2 + 4 * ty]);
            const float4 b4 = *reinterpret_cast<const float4*>(&sT[e * S2 + 4 * tx]);
            const float a[4] = {a4.x, a4.y, a4.z, a4.w};
            const float bb[4] = {b4.x, b4.y, b4.z, b4.w};
#pragma unroll
            for (int i = 0; i < 4; ++i)
#pragma unroll
                for (int j = 0; j < 4; ++j) acc[i][j] = fmaf(a[i], bb[j], acc[i][j]);
        }
#pragma unroll
        for (int i = 0; i < 4; ++i)
#pragma unroll
            for (int j = 0; j < 4; ++j)
                atomicAdd(&g_M[b * 4096 + (4 * ty + i) * 64 + (4 * tx + j)], acc[i][j]);
    }
}

// ---------------------------------------------------------------------------
// K3: out = M^T @ x via bf16-split tensor MMA.
// grid = 512 (4 batches x 128 segments of 128 tokens), 256 threads.
// x4.trans B-frags; __launch_bounds__(256,2) pins regs to 128 (no spills).
// ---------------------------------------------------------------------------
#define X3_STRIDE 136
#define MT_STRIDE 72
#define K3_SBYTES (2 * 64 * X3_STRIDE * 2 + 2 * 64 * MT_STRIDE * 2) // 53248

__global__ __launch_bounds__(256, 2) void out_kernel(const float* __restrict__ x,
                                                     const float* __restrict__ bp,
                                                     float* __restrict__ out) {
    extern __shared__ unsigned short sm3[];
    unsigned short* xhi = sm3;
    unsigned short* xlo = sm3 + 64 * X3_STRIDE;
    unsigned short* mhi = sm3 + 2 * 64 * X3_STRIDE;
    unsigned short* mlo = mhi + 64 * MT_STRIDE;

    const int b    = blockIdx.x >> 7;
    const int seg  = blockIdx.x & 127;
    const int n0   = seg * 128;
    const int tid  = threadIdx.x;
    const int lane = tid & 31;
    const int wid  = tid >> 5;

    const float* xb = x + (size_t)b * CCH * NTOK;
    float* ob = out + (size_t)b * CCH * NTOK;

    // fill x tile (convert to hi/lo): 2048 f4 / 256 thr = 8 each
#pragma unroll
    for (int r = 0; r < 8; ++r) {
        const int q  = r * 256 + tid;
        const int c  = q >> 5;
        const int t4 = q & 31;
        const float4 v = *reinterpret_cast<const float4*>(&xb[c * NTOK + n0 + 4 * t4]);
        unsigned h0, l0, h1, l1;
        split2(v.x, v.y, h0, l0);
        split2(v.z, v.w, h1, l1);
        *reinterpret_cast<uint2*>(&xhi[c * X3_STRIDE + 4 * t4]) = make_uint2(h0, h1);
        *reinterpret_cast<uint2*>(&xlo[c * X3_STRIDE + 4 * t4]) = make_uint2(l0, l1);
    }
    // fill Mt tiles: read fp32 g_M [cp][c], split + transpose -> [c][cp]
#pragma unroll
    for (int r = 0; r < 16; ++r) {
        const int q  = r * 256 + tid;   // 0..4095
        const int cp = q >> 6, c = q & 63;
        const float v = g_M[b * 4096 + q];
        const __nv_bfloat16 hh = __float2bfloat16(v);
        const __nv_bfloat16 ll = __float2bfloat16(v - __bfloat162float(hh));
        mhi[c * MT_STRIDE + cp] = __bfloat16_as_ushort(hh);
        mlo[c * MT_STRIDE + cp] = __bfloat16_as_ushort(ll);
    }
    __syncthreads();

    const int mt = wid & 3;         // c tile (16 rows)
    const int tg = wid >> 2;        // token group (64 tokens each)

    float acc[8][4];
#pragma unroll
    for (int j = 0; j < 8; ++j)
#pragma unroll
        for (int k = 0; k < 4; ++k) acc[j][k] = 0.f;

    const int aq   = lane >> 3;
    const int arow = 16 * mt + (aq & 1) * 8 + (lane & 7);
    const int acol_off = (aq >> 1) * 8;
    // B x4t lane address: row = K0 + (lane&15), col = T0 + ((lane>>4)<<3)
    const int bkrow = lane & 15;
    const int btcol = (lane >> 4) << 3;

#pragma unroll
    for (int kt = 0; kt < 4; ++kt) {
        const int K0 = 16 * kt;
        unsigned Ahi[4], Alo[4];
        ldm_x4(Ahi, cvs(&mhi[arow * MT_STRIDE + K0 + acol_off]));
        ldm_x4(Alo, cvs(&mlo[arow * MT_STRIDE + K0 + acol_off]));
        const int brow = K0 + bkrow;
#pragma unroll
        for (int p = 0; p < 4; ++p) {
            const int T0 = 64 * tg + 16 * p;
            unsigned Bhi[4], Blo[4];
            ldm_x4t(Bhi, cvs(&xhi[brow * X3_STRIDE + T0 + btcol]));
            ldm_x4t(Blo, cvs(&xlo[brow * X3_STRIDE + T0 + btcol]));
            mma_bf16(acc[2 * p],     Ahi, Bhi[0], Bhi[1]);
            mma_bf16(acc[2 * p],     Ahi, Blo[0], Blo[1]);
            mma_bf16(acc[2 * p],     Alo, Bhi[0], Bhi[1]);
            mma_bf16(acc[2 * p + 1], Ahi, Bhi[2], Bhi[3]);
            mma_bf16(acc[2 * p + 1], Ahi, Blo[2], Blo[3]);
            mma_bf16(acc[2 * p + 1], Alo, Bhi[2], Bhi[3]);
        }
    }

    const int g = lane >> 2, l = lane & 3;
    const int r0 = 16 * mt + g;
    const float bp0 = bp[r0], bp1 = bp[r0 + 8];
#pragma unroll
    for (int j = 0; j < 8; ++j) {
        const int tok = n0 + 64 * tg + 8 * j + 2 * l;
        *reinterpret_cast<float2*>(&ob[r0 * NTOK + tok]) =
            make_float2(acc[j][0] + bp0, acc[j][1] + bp0);
        *reinterpret_cast<float2*>(&ob[(r0 + 8) * NTOK + tok]) =
            make_float2(acc[j][2] + bp1, acc[j][3] + bp1);
    }
}

// ---------------------------------------------------------------------------
extern "C" void kernel_launch(void* const* d_in, const int* in_sizes, int n_in,
                              void* d_out, int out_size) {
    const float* x       = (const float*)d_in[0];
    const float* Wq      = (const float*)d_in[1];
    const float* Wk      = (const float*)d_in[2];
    const float* Wv      = (const float*)d_in[3];
    const float* Wp      = (const float*)d_in[4];
    const float* bp      = (const float*)d_in[5];
    const float* rescale = (const float*)d_in[6];
    float* out      = (float*)d_out;
    float* attn_out = out + OUT_ELEMS;

    cudaFuncSetAttribute(gram_kernel,
                         cudaFuncAttributeMaxDynamicSharedMemorySize, K1_SBYTES);
    cudaFuncSetAttribute(attn_small_kernel,
                         cudaFuncAttributeMaxDynamicSharedMemorySize, K2_SBYTES);
    cudaFuncSetAttribute(out_kernel,
                         cudaFuncAttributeMaxDynamicSharedMemorySize, K3_SBYTES);

    gram_kernel<<<256, 256, K1_SBYTES>>>(x);
    reduce_gram_kernel<<<16, 256>>>();
    attn_small_kernel<<<64, 256, K2_SBYTES>>>(Wq, Wk, Wv, Wp, rescale, attn_out);
    out_kernel<<<512, 256, K3_SBYTES>>>(x, bp, out);
}